// round 12
// baseline (speedup 1.0000x reference)
#include <cuda_runtime.h>
#include <cuda_fp16.h>
#include <math.h>
#include <stdint.h>

// ---------------------------------------------------------------------------
// Problem constants (B=16, Ci=Co=64, H=W=128, alpha=0.5)
// Exact algebra: conj(A) A = I  =>  y[b,o,h,w] = sum_i wc[o,i] x[b,i,h,w]
//                                             + bc[o]*u[h]*u[w],
// u = conj(A(alpha)) @ 1 (host-computed, passed as kernel param).
// Per 128-px tile: D[o=128][px=128] = W[128,64] @ X^T, W = [Wr;Wi] stacked.
// fp16 2-term split on W, X single fp16, fp32 accum, mma.sync.m16n8k16.
// Persistent CTAs (2/SM, 256 thr): A-HI fragments hoisted into registers
// across the tile loop (A-LO stays in smem, per-tile ldmatrix), X raw tiles
// prefetched with cp.async one tile ahead.
// ---------------------------------------------------------------------------
#define BATCH 16
#define CH    64
#define HDIM  128
#define HW    (HDIM*HDIM)        // 16384
#define THREADS 256
#define NTILES (BATCH*HW/128)    // 2048
#define GRID   296               // 148 SMs x 2 CTAs

// smem layout (bytes)
#define SM_AHI   0                    // fp16 W_hi [128 o][64 ch], SW128, 16384
#define SM_ALO   16384                // fp16 W_lo
#define SM_XF16  32768                // fp16 X [64 ch][128 px], 272B rows, 17408
#define SM_XRAW  50176                // fp32 X raw [64 ch][128 px], 32768
#define SM_G2    82944                // float2 g[128] = (gr,gi)   1024
#define SM_BSR   83968                // float[64]
#define SM_BSI   84224
#define SM_TOTAL 84480

#define XPITCH 272                    // 128px*2B + 16B pad

#define SW128(o) ((o) ^ (((o) >> 3) & 0x70))

struct UParam { float ur[128]; float ui[128]; };

__device__ __forceinline__ uint32_t smem_u32(const void* p) {
    uint32_t a;
    asm("{ .reg .u64 t; cvta.to.shared.u64 t, %1; cvt.u32.u64 %0, t; }"
        : "=r"(a) : "l"(p));
    return a;
}
__device__ __forceinline__ void ldsm4(uint32_t addr, uint32_t& r0, uint32_t& r1,
                                      uint32_t& r2, uint32_t& r3) {
    asm volatile("ldmatrix.sync.aligned.m8n8.x4.shared.b16 {%0,%1,%2,%3}, [%4];"
                 : "=r"(r0), "=r"(r1), "=r"(r2), "=r"(r3) : "r"(addr));
}
__device__ __forceinline__ void ldsm4t(uint32_t addr, uint32_t& r0, uint32_t& r1,
                                       uint32_t& r2, uint32_t& r3) {
    asm volatile("ldmatrix.sync.aligned.m8n8.x4.trans.shared.b16 {%0,%1,%2,%3}, [%4];"
                 : "=r"(r0), "=r"(r1), "=r"(r2), "=r"(r3) : "r"(addr));
}
__device__ __forceinline__ void mma16816(float* c, uint32_t a0, uint32_t a1,
                                         uint32_t a2, uint32_t a3,
                                         uint32_t b0, uint32_t b1) {
    asm volatile(
        "mma.sync.aligned.m16n8k16.row.col.f32.f16.f16.f32 "
        "{%0,%1,%2,%3}, {%4,%5,%6,%7}, {%8,%9}, {%0,%1,%2,%3};"
        : "+f"(c[0]), "+f"(c[1]), "+f"(c[2]), "+f"(c[3])
        : "r"(a0), "r"(a1), "r"(a2), "r"(a3), "r"(b0), "r"(b1));
}
__device__ __forceinline__ uint32_t packh2(float a, float b) {
    __half ha = __float2half_rn(a), hb = __float2half_rn(b);
    return ((uint32_t)__half_as_ushort(hb) << 16) | __half_as_ushort(ha);
}
__device__ __forceinline__ void cpasync16(uint32_t dst, const void* src) {
    asm volatile("cp.async.cg.shared.global [%0], [%1], 16;"
                 :: "r"(dst), "l"(src));
}

// ---------------------------------------------------------------------------
__global__ void __launch_bounds__(THREADS, 2)
spec_mma(const float* __restrict__ x,  const float* __restrict__ wr,
         const float* __restrict__ wi, const float* __restrict__ br,
         const float* __restrict__ bi, float* __restrict__ out, UParam up)
{
    extern __shared__ char smem[];
    const uint32_t sb = smem_u32(smem);
    const int tid  = threadIdx.x;
    const int lane = tid & 31;
    const int wo   = tid >> 5;
    const int mg   = wo & 3;             // m-group: 32 outputs
    const int ng   = wo >> 2;            // n-group: 64 pixels

    // ---- once per CTA: weights -> A smem [o][ch] fp16 hi/lo, SW128 ----
    #pragma unroll
    for (int r = 0; r < 8; ++r) {
        int f4 = r*THREADS + tid;        // 2048 = 128 o x 16 float4
        int o = f4 >> 4, k4 = f4 & 15;
        const float* src = (o < 64) ? (wr + o*64) : (wi + (o-64)*64);
        float4 v = ((const float4*)src)[k4];
        __half h0 = __float2half_rn(v.x), h1 = __float2half_rn(v.y);
        __half h2 = __float2half_rn(v.z), h3 = __float2half_rn(v.w);
        uint2 ph = make_uint2(((uint32_t)__half_as_ushort(h1) << 16) | __half_as_ushort(h0),
                              ((uint32_t)__half_as_ushort(h3) << 16) | __half_as_ushort(h2));
        uint2 pl = make_uint2(packh2(v.x - __half2float(h0), v.y - __half2float(h1)),
                              packh2(v.z - __half2float(h2), v.w - __half2float(h3)));
        uint32_t so = SW128((uint32_t)(o*128 + k4*8));
        *(uint2*)(smem + SM_AHI + so) = ph;
        *(uint2*)(smem + SM_ALO + so) = pl;
    }
    if (tid < 64) {
        ((float*)(smem + SM_BSR))[tid] = br[tid];
        ((float*)(smem + SM_BSI))[tid] = bi[tid];
    }

    // ---- prefetch raw x tile for first owned tile ----
    {
        int t0 = blockIdx.x;
        const float* xb = x + ((size_t)(t0 >> 7))*CH*HW + ((t0 & 127) << 7);
        #pragma unroll
        for (int r = 0; r < 8; ++r) {
            int c = r*THREADS + tid;                 // 0..2047 16B chunks
            int ch = c >> 5, of = c & 31;
            cpasync16(sb + SM_XRAW + ch*512 + of*16,
                      xb + (size_t)ch*HW + of*4);
        }
        asm volatile("cp.async.commit_group;");
    }

    // tile-invariant lane constants
    const int o0   = mg * 32;
    const int px0l = ng * 64;
    const uint32_t a_row0   = (uint32_t)((o0 + (lane & 15)) * 128);
    const uint32_t a_colsel = (uint32_t)((lane >> 4) * 16);
    const uint32_t x_lconst = (uint32_t)((lane & 15) * XPITCH +
                                         (lane >> 4) * 16 + px0l * 2);
    const int g  = lane >> 2;
    const int tg = lane & 3;
    const int pl = mg >> 1;              // 0 = re plane, 1 = im plane
    const float2* g2 = (const float2*)(smem + SM_G2);

    // ---- hoist A-HI fragments into registers (valid for ALL tiles) ----
    __syncthreads();                     // W smem tiles + bias complete
    uint32_t ahr[2][4][4];               // [m-tile][k][frag] = 32 regs
    #pragma unroll
    for (int k = 0; k < 4; ++k) {
        uint32_t a_off0 = SW128(a_row0 + (uint32_t)(k*32) + a_colsel);
        uint32_t a_off1 = SW128(a_row0 + (uint32_t)(16*128) + (uint32_t)(k*32) + a_colsel);
        ldsm4(sb + SM_AHI + a_off0, ahr[0][k][0], ahr[0][k][1], ahr[0][k][2], ahr[0][k][3]);
        ldsm4(sb + SM_AHI + a_off1, ahr[1][k][0], ahr[1][k][1], ahr[1][k][2], ahr[1][k][3]);
    }
    // tile-invariant bias scalars (rows o0+tt*16+g, +8)
    float brv[2][2], biv[2][2];
    {
        const float* bsr = (const float*)(smem + SM_BSR);
        const float* bsi = (const float*)(smem + SM_BSI);
        #pragma unroll
        for (int tt = 0; tt < 2; ++tt) {
            int oA = (o0 + tt*16 + g) & 63;
            brv[tt][0] = bsr[oA];     biv[tt][0] = bsi[oA];
            brv[tt][1] = bsr[oA + 8]; biv[tt][1] = bsi[oA + 8];
        }
    }

    for (int t = blockIdx.x; t < NTILES; t += GRID) {
        const int b    = t >> 7;
        const int hrow = t & 127;
        const int pix0 = hrow << 7;

        asm volatile("cp.async.wait_group 0;" ::: "memory");
        __syncthreads();

        // ---- convert XRAW (fp32) -> XF16, STS.128 ----
        #pragma unroll
        for (int r = 0; r < 4; ++r) {
            int c8 = r*THREADS + tid;                // 1024 = 64 ch x 16 groups
            int ch = c8 >> 4, p8 = c8 & 15;
            const float4* s = (const float4*)(smem + SM_XRAW + ch*512 + p8*32);
            float4 v0 = s[0], v1 = s[1];
            uint4 pk;
            pk.x = packh2(v0.x, v0.y); pk.y = packh2(v0.z, v0.w);
            pk.z = packh2(v1.x, v1.y); pk.w = packh2(v1.z, v1.w);
            *(uint4*)(smem + SM_XF16 + ch*XPITCH + p8*16) = pk;
        }
        if (tid < 128) {
            float uhr = up.ur[hrow], uhi = up.ui[hrow];
            float2 gg = make_float2(uhr*up.ur[tid] - uhi*up.ui[tid],
                                    uhr*up.ui[tid] + uhi*up.ur[tid]);
            ((float2*)(smem + SM_G2))[tid] = gg;
        }
        __syncthreads();

        // ---- prefetch next tile's raw x (overlaps mainloop + epilogue) ----
        int tn = t + GRID;
        if (tn < NTILES) {
            const float* xb = x + ((size_t)(tn >> 7))*CH*HW + ((tn & 127) << 7);
            #pragma unroll
            for (int r = 0; r < 8; ++r) {
                int c = r*THREADS + tid;
                int ch = c >> 5, of = c & 31;
                cpasync16(sb + SM_XRAW + ch*512 + of*16,
                          xb + (size_t)ch*HW + of*4);
            }
        }
        asm volatile("cp.async.commit_group;");

        // ---- mainloop: warp computes D[o: o0..+32][px: px0l..+64] ----
        float acc[2][8][4];
        #pragma unroll
        for (int tt = 0; tt < 2; ++tt)
            #pragma unroll
            for (int j = 0; j < 8; ++j)
                #pragma unroll
                for (int q = 0; q < 4; ++q) acc[tt][j][q] = 0.0f;

        #pragma unroll
        for (int k = 0; k < 4; ++k) {
            // A-LO for both m-tiles (A-HI lives in registers)
            uint32_t a_off0 = SW128(a_row0 + (uint32_t)(k*32) + a_colsel);
            uint32_t a_off1 = SW128(a_row0 + (uint32_t)(16*128) + (uint32_t)(k*32) + a_colsel);
            uint32_t al[2][4];
            ldsm4(sb + SM_ALO + a_off0, al[0][0], al[0][1], al[0][2], al[0][3]);
            ldsm4(sb + SM_ALO + a_off1, al[1][0], al[1][1], al[1][2], al[1][3]);
            uint32_t xk = x_lconst + (uint32_t)(k*16*XPITCH);

            #pragma unroll
            for (int p = 0; p < 4; ++p) {
                uint32_t bh0, bh1, bh2, bh3;
                uint32_t xoff = xk + (uint32_t)(p*32);
                ldsm4t(sb + SM_XF16 + xoff, bh0, bh1, bh2, bh3);
                #pragma unroll
                for (int tt = 0; tt < 2; ++tt) {
                    mma16816(acc[tt][2*p],   ahr[tt][k][0], ahr[tt][k][1], ahr[tt][k][2], ahr[tt][k][3], bh0, bh1);
                    mma16816(acc[tt][2*p+1], ahr[tt][k][0], ahr[tt][k][1], ahr[tt][k][2], ahr[tt][k][3], bh2, bh3);
                    mma16816(acc[tt][2*p],   al[tt][0], al[tt][1], al[tt][2], al[tt][3], bh0, bh1);
                    mma16816(acc[tt][2*p+1], al[tt][0], al[tt][1], al[tt][2], al[tt][3], bh2, bh3);
                }
            }
        }

        // ---- epilogue: add bc[o]*u[h]*u[w], store ----
        float* base = out + (size_t)pl*BATCH*CH*HW + (size_t)b*CH*HW + pix0 + px0l;

        #pragma unroll
        for (int tt = 0; tt < 2; ++tt) {
            int oA  = (o0 + tt*16 + g) & 63;             // rows oA and oA+8
            float brA = brv[tt][0], biA = biv[tt][0];
            float brB = brv[tt][1], biB = biv[tt][1];
            float* pA = base + (size_t)oA*HW;
            float* pB = pA + 8*HW;
            #pragma unroll
            for (int j = 0; j < 8; ++j) {
                int pxl = j*8 + 2*tg;                    // local px within 64
                float4 gg = *(const float4*)&g2[px0l + pxl];
                float bA0, bA1, bB0, bB1;
                if (pl == 0) {
                    bA0 = brA*gg.x - biA*gg.y;  bA1 = brA*gg.z - biA*gg.w;
                    bB0 = brB*gg.x - biB*gg.y;  bB1 = brB*gg.z - biB*gg.w;
                } else {
                    bA0 = brA*gg.y + biA*gg.x;  bA1 = brA*gg.w + biA*gg.z;
                    bB0 = brB*gg.y + biB*gg.x;  bB1 = brB*gg.w + biB*gg.z;
                }
                *(float2*)(pA + pxl) = make_float2(acc[tt][j][0] + bA0, acc[tt][j][1] + bA1);
                *(float2*)(pB + pxl) = make_float2(acc[tt][j][2] + bB0, acc[tt][j][3] + bB1);
            }
        }
    }
}

// ---------------------------------------------------------------------------
// Host: u = conj(A(alpha)) @ 1 for N=128, alpha=0.5 (Candan DFRFT pipeline),
// double precision. Host-only: runs at launch/capture time, not in replays.
// ---------------------------------------------------------------------------
static void host_jacobi_eigh(double* A, int n, double* V)
{
    for (int i = 0; i < n*n; ++i) V[i] = 0.0;
    for (int i = 0; i < n; ++i) V[i*n + i] = 1.0;
    for (int sweep = 0; sweep < 100; ++sweep) {
        double off = 0.0;
        for (int p = 0; p < n; ++p)
            for (int q = p+1; q < n; ++q) off += A[p*n+q]*A[p*n+q];
        if (off < 1e-24) break;
        for (int p = 0; p < n-1; ++p) {
            for (int q = p+1; q < n; ++q) {
                double apq = A[p*n+q];
                if (fabs(apq) < 1e-300) continue;
                double app = A[p*n+p], aqq = A[q*n+q];
                double theta = (aqq - app) / (2.0*apq);
                double t = ((theta >= 0.0) ? 1.0 : -1.0) /
                           (fabs(theta) + sqrt(theta*theta + 1.0));
                double c = 1.0/sqrt(t*t + 1.0), s = t*c;
                for (int k = 0; k < n; ++k) {
                    double akp = A[k*n+p], akq = A[k*n+q];
                    A[k*n+p] = c*akp - s*akq;
                    A[k*n+q] = s*akp + c*akq;
                }
                for (int k = 0; k < n; ++k) {
                    double apk = A[p*n+k], aqk = A[q*n+k];
                    A[p*n+k] = c*apk - s*aqk;
                    A[q*n+k] = s*apk + c*aqk;
                }
                for (int k = 0; k < n; ++k) {
                    double vkp = V[k*n+p], vkq = V[k*n+q];
                    V[k*n+p] = c*vkp - s*vkq;
                    V[k*n+q] = s*vkp + c*vkq;
                }
            }
        }
    }
}

static void sort_ascending_perm(const double* ev, int n, int* perm)
{
    for (int i = 0; i < n; ++i) perm[i] = i;
    for (int i = 1; i < n; ++i) {
        int pi = perm[i]; double v = ev[pi]; int j = i - 1;
        while (j >= 0 && ev[perm[j]] > v) { perm[j+1] = perm[j]; --j; }
        perm[j+1] = pi;
    }
}

static void compute_u_host(float* ur_out, float* ui_out)
{
    const int N = 128, R = 64;
    const double PI = 3.14159265358979323846264338327950288;
    static double S[128*128], P[128*128], T1[128*128], CS[128*128];
    static double C2[65*65], S2m[63*63], VC[65*65], VS[63*63];
    static double E[128*128];

    for (int i = 0; i < N*N; ++i) { S[i] = 0.0; P[i] = 0.0; E[i] = 0.0; }
    for (int i = 0; i < N; ++i) {
        S[i*N + (i+1)%N]   += 1.0;
        S[i*N + (i-1+N)%N] += 1.0;
        S[i*N + i]         += 2.0*cos(2.0*PI*i/N);
    }
    double c = 1.0/sqrt(2.0);
    P[0] = 1.0;
    for (int i = 1; i <= R-1; ++i) { P[i*N+i] = c;  P[i*N + (N-i)] = c; }
    P[R*N + R] = 1.0;
    for (int i = R+1; i < N; ++i) { P[i*N+i] = -c; P[i*N + (N-i)] = c; }
    for (int i = 0; i < N; ++i)
        for (int j = 0; j < N; ++j) {
            double a = 0.0;
            for (int k = 0; k < N; ++k) a += P[i*N+k]*S[k*N+j];
            T1[i*N+j] = a;
        }
    for (int i = 0; i < N; ++i)
        for (int j = 0; j < N; ++j) {
            double a = 0.0;
            for (int k = 0; k < N; ++k) a += T1[i*N+k]*P[j*N+k];
            CS[i*N+j] = a;
        }
    for (int i = 0; i < 65; ++i)
        for (int j = 0; j < 65; ++j) C2[i*65+j] = CS[i*N+j];
    for (int i = 0; i < 63; ++i)
        for (int j = 0; j < 63; ++j) S2m[i*63+j] = CS[(65+i)*N + 65+j];

    host_jacobi_eigh(C2, 65, VC);
    host_jacobi_eigh(S2m, 63, VS);
    double evC[65], evS[63];
    for (int i = 0; i < 65; ++i) evC[i] = C2[i*65+i];
    for (int i = 0; i < 63; ++i) evS[i] = S2m[i*63+i];
    int pc[65], ps[63];
    sort_ascending_perm(evC, 65, pc);
    sort_ascending_perm(evS, 63, ps);

    for (int m = 0; m < 65; ++m) {
        int src  = pc[64 - m];
        int ecol = (m < 64) ? 2*m : 127;
        for (int h = 0; h < N; ++h) {
            double a = 0.0;
            for (int j = 0; j < 65; ++j) a += P[h*N+j]*VC[j*65+src];
            E[h*N + ecol] = a;
        }
    }
    for (int m = 0; m < 63; ++m) {
        int src  = ps[62 - m];
        int ecol = 2*m + 1;
        for (int h = 0; h < N; ++h) {
            double a = 0.0;
            for (int j = 0; j < 63; ++j) a += P[h*N + 65 + j]*VS[j*63+src];
            E[h*N + ecol] = a;
        }
    }

    double uR[128], uI[128];
    for (int h = 0; h < N; ++h) { uR[h] = 0.0; uI[h] = 0.0; }
    for (int j = 0; j < N; ++j) {
        int kj = (j < 127) ? j : 128;
        double t = 0.0;
        for (int h = 0; h < N; ++h) t += E[h*N+j];
        double ph = PI * (double)kj / 4.0;
        double cr = cos(ph)*t, ci = sin(ph)*t;
        for (int h = 0; h < N; ++h) {
            uR[h] += E[h*N+j]*cr;
            uI[h] += E[h*N+j]*ci;
        }
    }
    for (int h = 0; h < N; ++h) { ur_out[h] = (float)uR[h]; ui_out[h] = (float)uI[h]; }
}

// ---------------------------------------------------------------------------
extern "C" void kernel_launch(void* const* d_in, const int* in_sizes, int n_in,
                              void* d_out, int out_size)
{
    (void)in_sizes; (void)n_in; (void)out_size;
    UParam up;
    compute_u_host(up.ur, up.ui);   // host-only; not part of the captured graph

    cudaFuncSetAttribute(spec_mma,
                         cudaFuncAttributeMaxDynamicSharedMemorySize, SM_TOTAL);
    spec_mma<<<GRID, THREADS, SM_TOTAL>>>(
        (const float*)d_in[0], (const float*)d_in[1], (const float*)d_in[2],
        (const float*)d_in[3], (const float*)d_in[4], (float*)d_out, up);
}

// round 13
// speedup vs baseline: 1.3065x; 1.3065x over previous
#include <cuda_runtime.h>
#include <cuda_fp16.h>
#include <math.h>
#include <stdint.h>

// ---------------------------------------------------------------------------
// Problem constants (B=16, Ci=Co=64, H=W=128, alpha=0.5)
// Exact algebra: conj(A) A = I  =>  y[b,o,h,w] = sum_i wc[o,i] x[b,i,h,w]
//                                             + bc[o]*u[h]*u[w],
// u = conj(A(alpha)) @ 1 (host-computed, passed as kernel param).
// Per 128-px tile: D[o=128][px=128] = W[128,64] @ X^T, W = [Wr;Wi] stacked.
// SINGLE fp16 for both W and X (error ~2.9e-4 << 1e-3 gate), fp32 accum,
// mma.sync.m16n8k16. Persistent CTAs (2/SM): W converted once per CTA;
// X raw tiles prefetched with cp.async one tile ahead (structure == R9).
// ---------------------------------------------------------------------------
#define BATCH 16
#define CH    64
#define HDIM  128
#define HW    (HDIM*HDIM)        // 16384
#define THREADS 256
#define NTILES (BATCH*HW/128)    // 2048
#define GRID   296               // 148 SMs x 2 CTAs

// smem layout (bytes)
#define SM_AHI   0                    // fp16 W [128 o][64 ch], SW128, 16384
#define SM_XF16  16384                // fp16 X [64 ch][128 px], 272B rows, 17408
#define SM_XRAW  33792                // fp32 X raw [64 ch][128 px], 32768
#define SM_G2    66560                // float2 g[128] = (gr,gi)   1024
#define SM_BSR   67584                // float[64]
#define SM_BSI   67840
#define SM_TOTAL 68096

#define XPITCH 272                    // 128px*2B + 16B pad

#define SW128(o) ((o) ^ (((o) >> 3) & 0x70))

struct UParam { float ur[128]; float ui[128]; };

__device__ __forceinline__ uint32_t smem_u32(const void* p) {
    uint32_t a;
    asm("{ .reg .u64 t; cvta.to.shared.u64 t, %1; cvt.u32.u64 %0, t; }"
        : "=r"(a) : "l"(p));
    return a;
}
__device__ __forceinline__ void ldsm4(uint32_t addr, uint32_t& r0, uint32_t& r1,
                                      uint32_t& r2, uint32_t& r3) {
    asm volatile("ldmatrix.sync.aligned.m8n8.x4.shared.b16 {%0,%1,%2,%3}, [%4];"
                 : "=r"(r0), "=r"(r1), "=r"(r2), "=r"(r3) : "r"(addr));
}
__device__ __forceinline__ void ldsm4t(uint32_t addr, uint32_t& r0, uint32_t& r1,
                                       uint32_t& r2, uint32_t& r3) {
    asm volatile("ldmatrix.sync.aligned.m8n8.x4.trans.shared.b16 {%0,%1,%2,%3}, [%4];"
                 : "=r"(r0), "=r"(r1), "=r"(r2), "=r"(r3) : "r"(addr));
}
__device__ __forceinline__ void mma16816(float* c, uint32_t a0, uint32_t a1,
                                         uint32_t a2, uint32_t a3,
                                         uint32_t b0, uint32_t b1) {
    asm volatile(
        "mma.sync.aligned.m16n8k16.row.col.f32.f16.f16.f32 "
        "{%0,%1,%2,%3}, {%4,%5,%6,%7}, {%8,%9}, {%0,%1,%2,%3};"
        : "+f"(c[0]), "+f"(c[1]), "+f"(c[2]), "+f"(c[3])
        : "r"(a0), "r"(a1), "r"(a2), "r"(a3), "r"(b0), "r"(b1));
}
__device__ __forceinline__ uint32_t packh2(float a, float b) {
    __half ha = __float2half_rn(a), hb = __float2half_rn(b);
    return ((uint32_t)__half_as_ushort(hb) << 16) | __half_as_ushort(ha);
}
__device__ __forceinline__ void cpasync16(uint32_t dst, const void* src) {
    asm volatile("cp.async.cg.shared.global [%0], [%1], 16;"
                 :: "r"(dst), "l"(src));
}

// ---------------------------------------------------------------------------
__global__ void __launch_bounds__(THREADS, 2)
spec_mma(const float* __restrict__ x,  const float* __restrict__ wr,
         const float* __restrict__ wi, const float* __restrict__ br,
         const float* __restrict__ bi, float* __restrict__ out, UParam up)
{
    extern __shared__ char smem[];
    const uint32_t sb = smem_u32(smem);
    const int tid  = threadIdx.x;
    const int lane = tid & 31;
    const int wo   = tid >> 5;
    const int mg   = wo & 3;             // m-group: 32 outputs
    const int ng   = wo >> 2;            // n-group: 64 pixels

    // ---- once per CTA: weights -> A smem [o][ch] fp16, SW128 ----
    #pragma unroll
    for (int r = 0; r < 8; ++r) {
        int f4 = r*THREADS + tid;        // 2048 = 128 o x 16 float4
        int o = f4 >> 4, k4 = f4 & 15;
        const float* src = (o < 64) ? (wr + o*64) : (wi + (o-64)*64);
        float4 v = ((const float4*)src)[k4];
        uint2 ph = make_uint2(packh2(v.x, v.y), packh2(v.z, v.w));
        uint32_t so = SW128((uint32_t)(o*128 + k4*8));
        *(uint2*)(smem + SM_AHI + so) = ph;
    }
    if (tid < 64) {
        ((float*)(smem + SM_BSR))[tid] = br[tid];
        ((float*)(smem + SM_BSI))[tid] = bi[tid];
    }

    // ---- prefetch raw x tile for first owned tile ----
    {
        int t0 = blockIdx.x;
        const float* xb = x + ((size_t)(t0 >> 7))*CH*HW + ((t0 & 127) << 7);
        #pragma unroll
        for (int r = 0; r < 8; ++r) {
            int c = r*THREADS + tid;                 // 0..2047 16B chunks
            int ch = c >> 5, of = c & 31;
            cpasync16(sb + SM_XRAW + ch*512 + of*16,
                      xb + (size_t)ch*HW + of*4);
        }
        asm volatile("cp.async.commit_group;");
    }

    // tile-invariant lane constants
    const int o0   = mg * 32;
    const int px0l = ng * 64;
    const uint32_t a_row0   = (uint32_t)((o0 + (lane & 15)) * 128);
    const uint32_t a_colsel = (uint32_t)((lane >> 4) * 16);
    const uint32_t x_lconst = (uint32_t)((lane & 15) * XPITCH +
                                         (lane >> 4) * 16 + px0l * 2);
    const int g  = lane >> 2;
    const int tg = lane & 3;
    const int pl = mg >> 1;              // 0 = re plane, 1 = im plane
    const float* bsr = (const float*)(smem + SM_BSR);
    const float* bsi = (const float*)(smem + SM_BSI);
    const float2* g2 = (const float2*)(smem + SM_G2);

    for (int t = blockIdx.x; t < NTILES; t += GRID) {
        const int b    = t >> 7;
        const int hrow = t & 127;
        const int pix0 = hrow << 7;

        asm volatile("cp.async.wait_group 0;" ::: "memory");
        __syncthreads();

        // ---- convert XRAW (fp32) -> XF16, STS.128 ----
        #pragma unroll
        for (int r = 0; r < 4; ++r) {
            int c8 = r*THREADS + tid;                // 1024 = 64 ch x 16 groups
            int ch = c8 >> 4, p8 = c8 & 15;
            const float4* s = (const float4*)(smem + SM_XRAW + ch*512 + p8*32);
            float4 v0 = s[0], v1 = s[1];
            uint4 pk;
            pk.x = packh2(v0.x, v0.y); pk.y = packh2(v0.z, v0.w);
            pk.z = packh2(v1.x, v1.y); pk.w = packh2(v1.z, v1.w);
            *(uint4*)(smem + SM_XF16 + ch*XPITCH + p8*16) = pk;
        }
        if (tid < 128) {
            float uhr = up.ur[hrow], uhi = up.ui[hrow];
            float2 gg = make_float2(uhr*up.ur[tid] - uhi*up.ui[tid],
                                    uhr*up.ui[tid] + uhi*up.ur[tid]);
            ((float2*)(smem + SM_G2))[tid] = gg;
        }
        __syncthreads();

        // ---- prefetch next tile's raw x (overlaps mainloop + epilogue) ----
        int tn = t + GRID;
        if (tn < NTILES) {
            const float* xb = x + ((size_t)(tn >> 7))*CH*HW + ((tn & 127) << 7);
            #pragma unroll
            for (int r = 0; r < 8; ++r) {
                int c = r*THREADS + tid;
                int ch = c >> 5, of = c & 31;
                cpasync16(sb + SM_XRAW + ch*512 + of*16,
                          xb + (size_t)ch*HW + of*4);
            }
        }
        asm volatile("cp.async.commit_group;");

        // ---- mainloop: warp computes D[o: o0..+32][px: px0l..+64] ----
        float acc[2][8][4];
        #pragma unroll
        for (int tt = 0; tt < 2; ++tt)
            #pragma unroll
            for (int j = 0; j < 8; ++j)
                #pragma unroll
                for (int q = 0; q < 4; ++q) acc[tt][j][q] = 0.0f;

        #pragma unroll
        for (int k = 0; k < 4; ++k) {
            uint32_t a_off0 = SW128(a_row0 + (uint32_t)(k*32) + a_colsel);
            uint32_t a_off1 = SW128(a_row0 + (uint32_t)(16*128) + (uint32_t)(k*32) + a_colsel);
            uint32_t ah[2][4];
            ldsm4(sb + SM_AHI + a_off0, ah[0][0], ah[0][1], ah[0][2], ah[0][3]);
            ldsm4(sb + SM_AHI + a_off1, ah[1][0], ah[1][1], ah[1][2], ah[1][3]);
            uint32_t xk = x_lconst + (uint32_t)(k*16*XPITCH);

            #pragma unroll
            for (int p = 0; p < 4; ++p) {
                uint32_t bh0, bh1, bh2, bh3;
                uint32_t xoff = xk + (uint32_t)(p*32);
                ldsm4t(sb + SM_XF16 + xoff, bh0, bh1, bh2, bh3);
                #pragma unroll
                for (int tt = 0; tt < 2; ++tt) {
                    mma16816(acc[tt][2*p],   ah[tt][0], ah[tt][1], ah[tt][2], ah[tt][3], bh0, bh1);
                    mma16816(acc[tt][2*p+1], ah[tt][0], ah[tt][1], ah[tt][2], ah[tt][3], bh2, bh3);
                }
            }
        }

        // ---- epilogue: add bc[o]*u[h]*u[w], store ----
        float* base = out + (size_t)pl*BATCH*CH*HW + (size_t)b*CH*HW + pix0 + px0l;

        #pragma unroll
        for (int tt = 0; tt < 2; ++tt) {
            int oA  = (o0 + tt*16 + g) & 63;             // rows oA and oA+8
            float brA = bsr[oA],     biA = bsi[oA];
            float brB = bsr[oA + 8], biB = bsi[oA + 8];
            float* pA = base + (size_t)oA*HW;
            float* pB = pA + 8*HW;
            #pragma unroll
            for (int j = 0; j < 8; ++j) {
                int pxl = j*8 + 2*tg;                    // local px within 64
                float4 gg = *(const float4*)&g2[px0l + pxl];
                float bA0, bA1, bB0, bB1;
                if (pl == 0) {
                    bA0 = brA*gg.x - biA*gg.y;  bA1 = brA*gg.z - biA*gg.w;
                    bB0 = brB*gg.x - biB*gg.y;  bB1 = brB*gg.z - biB*gg.w;
                } else {
                    bA0 = brA*gg.y + biA*gg.x;  bA1 = brA*gg.w + biA*gg.z;
                    bB0 = brB*gg.y + biB*gg.x;  bB1 = brB*gg.w + biB*gg.z;
                }
                *(float2*)(pA + pxl) = make_float2(acc[tt][j][0] + bA0, acc[tt][j][1] + bA1);
                *(float2*)(pB + pxl) = make_float2(acc[tt][j][2] + bB0, acc[tt][j][3] + bB1);
            }
        }
    }
}

// ---------------------------------------------------------------------------
// Host: u = conj(A(alpha)) @ 1 for N=128, alpha=0.5 (Candan DFRFT pipeline),
// double precision. Host-only: runs at launch/capture time, not in replays.
// ---------------------------------------------------------------------------
static void host_jacobi_eigh(double* A, int n, double* V)
{
    for (int i = 0; i < n*n; ++i) V[i] = 0.0;
    for (int i = 0; i < n; ++i) V[i*n + i] = 1.0;
    for (int sweep = 0; sweep < 100; ++sweep) {
        double off = 0.0;
        for (int p = 0; p < n; ++p)
            for (int q = p+1; q < n; ++q) off += A[p*n+q]*A[p*n+q];
        if (off < 1e-24) break;
        for (int p = 0; p < n-1; ++p) {
            for (int q = p+1; q < n; ++q) {
                double apq = A[p*n+q];
                if (fabs(apq) < 1e-300) continue;
                double app = A[p*n+p], aqq = A[q*n+q];
                double theta = (aqq - app) / (2.0*apq);
                double t = ((theta >= 0.0) ? 1.0 : -1.0) /
                           (fabs(theta) + sqrt(theta*theta + 1.0));
                double c = 1.0/sqrt(t*t + 1.0), s = t*c;
                for (int k = 0; k < n; ++k) {
                    double akp = A[k*n+p], akq = A[k*n+q];
                    A[k*n+p] = c*akp - s*akq;
                    A[k*n+q] = s*akp + c*akq;
                }
                for (int k = 0; k < n; ++k) {
                    double apk = A[p*n+k], aqk = A[q*n+k];
                    A[p*n+k] = c*apk - s*aqk;
                    A[q*n+k] = s*apk + c*aqk;
                }
                for (int k = 0; k < n; ++k) {
                    double vkp = V[k*n+p], vkq = V[k*n+q];
                    V[k*n+p] = c*vkp - s*vkq;
                    V[k*n+q] = s*vkp + c*vkq;
                }
            }
        }
    }
}

static void sort_ascending_perm(const double* ev, int n, int* perm)
{
    for (int i = 0; i < n; ++i) perm[i] = i;
    for (int i = 1; i < n; ++i) {
        int pi = perm[i]; double v = ev[pi]; int j = i - 1;
        while (j >= 0 && ev[perm[j]] > v) { perm[j+1] = perm[j]; --j; }
        perm[j+1] = pi;
    }
}

static void compute_u_host(float* ur_out, float* ui_out)
{
    const int N = 128, R = 64;
    const double PI = 3.14159265358979323846264338327950288;
    static double S[128*128], P[128*128], T1[128*128], CS[128*128];
    static double C2[65*65], S2m[63*63], VC[65*65], VS[63*63];
    static double E[128*128];

    for (int i = 0; i < N*N; ++i) { S[i] = 0.0; P[i] = 0.0; E[i] = 0.0; }
    for (int i = 0; i < N; ++i) {
        S[i*N + (i+1)%N]   += 1.0;
        S[i*N + (i-1+N)%N] += 1.0;
        S[i*N + i]         += 2.0*cos(2.0*PI*i/N);
    }
    double c = 1.0/sqrt(2.0);
    P[0] = 1.0;
    for (int i = 1; i <= R-1; ++i) { P[i*N+i] = c;  P[i*N + (N-i)] = c; }
    P[R*N + R] = 1.0;
    for (int i = R+1; i < N; ++i) { P[i*N+i] = -c; P[i*N + (N-i)] = c; }
    for (int i = 0; i < N; ++i)
        for (int j = 0; j < N; ++j) {
            double a = 0.0;
            for (int k = 0; k < N; ++k) a += P[i*N+k]*S[k*N+j];
            T1[i*N+j] = a;
        }
    for (int i = 0; i < N; ++i)
        for (int j = 0; j < N; ++j) {
            double a = 0.0;
            for (int k = 0; k < N; ++k) a += T1[i*N+k]*P[j*N+k];
            CS[i*N+j] = a;
        }
    for (int i = 0; i < 65; ++i)
        for (int j = 0; j < 65; ++j) C2[i*65+j] = CS[i*N+j];
    for (int i = 0; i < 63; ++i)
        for (int j = 0; j < 63; ++j) S2m[i*63+j] = CS[(65+i)*N + 65+j];

    host_jacobi_eigh(C2, 65, VC);
    host_jacobi_eigh(S2m, 63, VS);
    double evC[65], evS[63];
    for (int i = 0; i < 65; ++i) evC[i] = C2[i*65+i];
    for (int i = 0; i < 63; ++i) evS[i] = S2m[i*63+i];
    int pc[65], ps[63];
    sort_ascending_perm(evC, 65, pc);
    sort_ascending_perm(evS, 63, ps);

    for (int m = 0; m < 65; ++m) {
        int src  = pc[64 - m];
        int ecol = (m < 64) ? 2*m : 127;
        for (int h = 0; h < N; ++h) {
            double a = 0.0;
            for (int j = 0; j < 65; ++j) a += P[h*N+j]*VC[j*65+src];
            E[h*N + ecol] = a;
        }
    }
    for (int m = 0; m < 63; ++m) {
        int src  = ps[62 - m];
        int ecol = 2*m + 1;
        for (int h = 0; h < N; ++h) {
            double a = 0.0;
            for (int j = 0; j < 63; ++j) a += P[h*N + 65 + j]*VS[j*63+src];
            E[h*N + ecol] = a;
        }
    }

    double uR[128], uI[128];
    for (int h = 0; h < N; ++h) { uR[h] = 0.0; uI[h] = 0.0; }
    for (int j = 0; j < N; ++j) {
        int kj = (j < 127) ? j : 128;
        double t = 0.0;
        for (int h = 0; h < N; ++h) t += E[h*N+j];
        double ph = PI * (double)kj / 4.0;
        double cr = cos(ph)*t, ci = sin(ph)*t;
        for (int h = 0; h < N; ++h) {
            uR[h] += E[h*N+j]*cr;
            uI[h] += E[h*N+j]*ci;
        }
    }
    for (int h = 0; h < N; ++h) { ur_out[h] = (float)uR[h]; ui_out[h] = (float)uI[h]; }
}

// ---------------------------------------------------------------------------
extern "C" void kernel_launch(void* const* d_in, const int* in_sizes, int n_in,
                              void* d_out, int out_size)
{
    (void)in_sizes; (void)n_in; (void)out_size;
    UParam up;
    compute_u_host(up.ur, up.ui);   // host-only; not part of the captured graph

    cudaFuncSetAttribute(spec_mma,
                         cudaFuncAttributeMaxDynamicSharedMemorySize, SM_TOTAL);
    spec_mma<<<GRID, THREADS, SM_TOTAL>>>(
        (const float*)d_in[0], (const float*)d_in[1], (const float*)d_in[2],
        (const float*)d_in[3], (const float*)d_in[4], (float*)d_out, up);
}